// round 14
// baseline (speedup 1.0000x reference)
#include <cuda_runtime.h>
#include <stdint.h>

#define B_N    2048
#define D_N    1024
#define POOL_N 2048
#define HARD_N 128
#define EXTRA_N 64
#define AFIN_N 256
#define NFIN   192

#define BM 256
#define BN 128

/* ------------------------------------------------------------------ */
/* Scratch                                                            */
/* ------------------------------------------------------------------ */
__device__ float  g_Apool[D_N * POOL_N];
__device__ float  g_means[D_N];
__device__ float  g_ut[POOL_N * B_N];
__device__ float  g_u2t[AFIN_N * B_N];
__device__ double g_losses[POOL_N];
__device__ int    g_ranked[HARD_N];
__device__ float  g_H[HARD_N * D_N];
__device__ float  g_G[HARD_N * HARD_N];
__device__ float  g_T[HARD_N * HARD_N];
__device__ float  g_Q[HARD_N * D_N];
__device__ float  g_R[D_N * EXTRA_N];
__device__ float  g_C[HARD_N * EXTRA_N];
__device__ float  g_Afin[D_N * AFIN_N];
__device__ double g_floss[NFIN];

/* ---------------- packed f32x2 helpers ---------------------------- */
__device__ __forceinline__ unsigned long long bcast2(float x) {
    unsigned long long r;
    asm("mov.b64 %0, {%1, %1};" : "=l"(r) : "f"(x));
    return r;
}
__device__ __forceinline__ void fma2(unsigned long long& d,
                                     unsigned long long a,
                                     unsigned long long b) {
    asm("fma.rn.f32x2 %0, %1, %2, %0;" : "+l"(d) : "l"(a), "l"(b));
}
__device__ __forceinline__ float2 unpk2(unsigned long long v) {
    float2 r;
    asm("mov.b64 {%0, %1}, %2;" : "=f"(r.x), "=f"(r.y) : "l"(v));
    return r;
}

/* ------------------------------------------------------------------ */
/* JAX threefry2x32 (partitionable)                                   */
/* ------------------------------------------------------------------ */
__device__ __forceinline__ uint32_t rotl32(uint32_t x, int r) {
    return (x << r) | (x >> (32 - r));
}
__device__ __forceinline__ void threefry2x32(uint32_t k0, uint32_t k1,
                                             uint32_t x0, uint32_t x1,
                                             uint32_t& o0, uint32_t& o1) {
    uint32_t ks2 = k0 ^ k1 ^ 0x1BD11BDAu;
    x0 += k0; x1 += k1;
#define TFR(r) { x0 += x1; x1 = rotl32(x1, (r)); x1 ^= x0; }
    TFR(13) TFR(15) TFR(26) TFR(6)  x0 += k1;  x1 += ks2 + 1u;
    TFR(17) TFR(29) TFR(16) TFR(24) x0 += ks2; x1 += k0  + 2u;
    TFR(13) TFR(15) TFR(26) TFR(6)  x0 += k0;  x1 += k1  + 3u;
    TFR(17) TFR(29) TFR(16) TFR(24) x0 += k1;  x1 += ks2 + 4u;
    TFR(13) TFR(15) TFR(26) TFR(6)  x0 += ks2; x1 += k0  + 5u;
#undef TFR
    o0 = x0; o1 = x1;
}
__device__ __forceinline__ float erfinv_xla(float x) {
    float w = -log1pf(-x * x);
    float p;
    if (w < 5.0f) {
        w -= 2.5f;
        p = 2.81022636e-08f;
        p = fmaf(p, w, 3.43273939e-07f);
        p = fmaf(p, w, -3.5233877e-06f);
        p = fmaf(p, w, -4.39150654e-06f);
        p = fmaf(p, w, 0.00021858087f);
        p = fmaf(p, w, -0.00125372503f);
        p = fmaf(p, w, -0.00417768164f);
        p = fmaf(p, w, 0.246640727f);
        p = fmaf(p, w, 1.50140941f);
    } else {
        w = sqrtf(w) - 3.0f;
        p = -0.000200214257f;
        p = fmaf(p, w, 0.000100950558f);
        p = fmaf(p, w, 0.00134934322f);
        p = fmaf(p, w, -0.00367342844f);
        p = fmaf(p, w, 0.00573950773f);
        p = fmaf(p, w, -0.0076224613f);
        p = fmaf(p, w, 0.00943887047f);
        p = fmaf(p, w, 1.00167406f);
        p = fmaf(p, w, 2.83297682f);
    }
    return p * x;
}
__device__ __forceinline__ float bits_to_normal(uint32_t b) {
    float f = __uint_as_float((b >> 9) | 0x3f800000u) - 1.0f;
    const float minv = -0.99999994f;
    float u = fmaf(f, 2.0f, minv);
    u = fmaxf(u, minv);
    return 1.41421356f * erfinv_xla(u);
}

/* ------------------------------------------------------------------ */
/* Fused setup: pool gen, colmean, extra gen                          */
/* ------------------------------------------------------------------ */
#define SETUP_POOL_BLKS  (D_N * POOL_N / 256)
#define SETUP_CM_BLKS    16
#define SETUP_EXTRA_BLKS (D_N * EXTRA_N / 256)

__global__ void __launch_bounds__(256) setup_kernel(const float* __restrict__ z,
                                                    const int* __restrict__ seed_ptr) {
    int b = blockIdx.x;
    if (b < SETUP_POOL_BLKS) {
        int i = b * 256 + threadIdx.x;
        uint32_t k1 = (uint32_t)seed_ptr[0];
        uint32_t o0, o1;
        threefry2x32(0u, k1, 0u, (uint32_t)i, o0, o1);
        g_Apool[i] = bits_to_normal(o0 ^ o1);
    } else if (b < SETUP_POOL_BLKS + SETUP_CM_BLKS) {
        __shared__ float2 sm[4][64];
        int xb = b - SETUP_POOL_BLKS;
        int x = threadIdx.x & 63, y = threadIdx.x >> 6;
        int c = xb * 64 + x;
        float s = 0.f, comp = 0.f;
        for (int r = y; r < B_N; r += 4) {
            float v = z[(size_t)r * D_N + c];
            float yv = v - comp;
            float t = s + yv;
            comp = (t - s) - yv;
            s = t;
        }
        sm[y][x] = make_float2(s, comp);
        __syncthreads();
        if (y == 0) {
            double tot = 0.0;
            for (int w = 0; w < 4; w++) {
                float2 p = sm[w][x];
                tot += (double)p.x - (double)p.y;
            }
            g_means[c] = (float)(tot * (1.0 / 2048.0));
        }
    } else {
        int i = (b - SETUP_POOL_BLKS - SETUP_CM_BLKS) * 256 + threadIdx.x;
        uint32_t k1 = (uint32_t)(seed_ptr[0] + 9991);
        uint32_t o0, o1;
        threefry2x32(0u, k1, 0u, (uint32_t)i, o0, o1);
        g_R[i] = bits_to_normal(o0 ^ o1);
    }
}

/* ------------------------------------------------------------------ */
/* Column normalize                                                   */
/* ------------------------------------------------------------------ */
__device__ __forceinline__ void norm_cols_body(float* A, int nc, int col) {
    __shared__ float2 sm[16][64];
    __shared__ float sden[64];
    int x = threadIdx.x, y = threadIdx.y;
    float s = 0.f, comp = 0.f;
    for (int r = 0; r < 64; r++) {
        int d = y * 64 + r;
        float v = A[(size_t)d * nc + col];
        float v2 = v * v;
        float yv = v2 - comp;
        float t = s + yv;
        comp = (t - s) - yv;
        s = t;
    }
    sm[y][x] = make_float2(s, comp);
    __syncthreads();
    if (y == 0) {
        double tot = 0.0;
        for (int w = 0; w < 16; w++) {
            float2 p = sm[w][x];
            tot += (double)p.x - (double)p.y;
        }
        sden[x] = (float)sqrt(tot) + 1e-12f;
    }
    __syncthreads();
    float den = sden[x];
    for (int r = 0; r < 64; r++) {
        int d = y * 64 + r;
        A[(size_t)d * nc + col] /= den;
    }
}

__global__ void norm_comb_kernel() {
    if (blockIdx.x < 32)
        norm_cols_body(g_Apool, POOL_N, blockIdx.x * 64 + threadIdx.x);
    else
        norm_cols_body(g_R, EXTRA_N, threadIdx.x);
}

__global__ void norm_cols_kernel(int which) {
    float* A = which ? g_R : g_Apool;
    int nc   = which ? EXTRA_N : POOL_N;
    norm_cols_body(A, nc, blockIdx.x * 64 + threadIdx.x);
}

/* ------------------------------------------------------------------ */
/* GEMM0: 256x128, 512 thr, f32x2, double-buffered (R11/R13 version)  */
/* ------------------------------------------------------------------ */
__global__ void __launch_bounds__(512, 1) gemm0_kernel(const float* __restrict__ z) {
    __shared__ __align__(16) float As[2][8][BM + 4];
    __shared__ __align__(16) float Bs[2][8][BN + 4];

    int tid = threadIdx.x;
    int tx = tid & 15;
    int ty = tid >> 4;
    int m0 = blockIdx.y * BM, n0 = blockIdx.x * BN;

    int a_row = tid >> 1;
    int a_k4  = (tid & 1) * 4;
    int b_k   = tid >> 6;
    int b_n2  = (tid & 63) * 2;

    const float* Ap = z + (size_t)(m0 + a_row) * D_N + a_k4;
    const float* Bp = g_Apool + (size_t)b_k * POOL_N + n0 + b_n2;

    unsigned long long acc[8][4];
#pragma unroll
    for (int i = 0; i < 8; i++)
#pragma unroll
        for (int jp = 0; jp < 4; jp++) acc[i][jp] = 0ull;

    float4 av = *(const float4*)Ap;
    float4 mv = *(const float4*)(g_means + a_k4);
    float2 bv = *(const float2*)Bp;

    for (int c = 0; c < D_N / 8; c++) {
        int buf = c & 1;
        As[buf][a_k4 + 0][a_row] = av.x - mv.x;
        As[buf][a_k4 + 1][a_row] = av.y - mv.y;
        As[buf][a_k4 + 2][a_row] = av.z - mv.z;
        As[buf][a_k4 + 3][a_row] = av.w - mv.w;
        *(float2*)&Bs[buf][b_k][b_n2] = bv;
        __syncthreads();
        if (c + 1 < D_N / 8) {
            int k0 = (c + 1) * 8;
            av = *(const float4*)(Ap + k0);
            mv = *(const float4*)(g_means + k0 + a_k4);
            bv = *(const float2*)(Bp + (size_t)k0 * POOL_N);
        }
#pragma unroll
        for (int kk = 0; kk < 8; kk++) {
            float4 a0 = *(const float4*)&As[buf][kk][ty * 8];
            float4 a1 = *(const float4*)&As[buf][kk][ty * 8 + 4];
            ulonglong2 b0 = *(const ulonglong2*)&Bs[buf][kk][tx * 8];
            ulonglong2 b1 = *(const ulonglong2*)&Bs[buf][kk][tx * 8 + 4];
            unsigned long long a2[8];
            a2[0] = bcast2(a0.x); a2[1] = bcast2(a0.y);
            a2[2] = bcast2(a0.z); a2[3] = bcast2(a0.w);
            a2[4] = bcast2(a1.x); a2[5] = bcast2(a1.y);
            a2[6] = bcast2(a1.z); a2[7] = bcast2(a1.w);
#pragma unroll
            for (int i = 0; i < 8; i++) {
                fma2(acc[i][0], a2[i], b0.x);
                fma2(acc[i][1], a2[i], b0.y);
                fma2(acc[i][2], a2[i], b1.x);
                fma2(acc[i][3], a2[i], b1.y);
            }
        }
    }

#pragma unroll
    for (int jp = 0; jp < 4; jp++) {
        float lo[8], hi[8];
#pragma unroll
        for (int i = 0; i < 8; i++) {
            float2 p = unpk2(acc[i][jp]);
            lo[i] = p.x; hi[i] = p.y;
        }
        int ne = n0 + tx * 8 + 2 * jp;
        float* be = &g_ut[(size_t)ne * B_N + m0 + ty * 8];
        float* bo = &g_ut[(size_t)(ne + 1) * B_N + m0 + ty * 8];
        *(float4*)be       = make_float4(lo[0], lo[1], lo[2], lo[3]);
        *(float4*)(be + 4) = make_float4(lo[4], lo[5], lo[6], lo[7]);
        *(float4*)bo       = make_float4(hi[0], hi[1], hi[2], hi[3]);
        *(float4*)(bo + 4) = make_float4(hi[4], hi[5], hi[6], hi[7]);
    }
}

/* ------------------------------------------------------------------ */
/* GEMM1 (final): 64x64 tiles, f32x2                                  */
/* ------------------------------------------------------------------ */
__global__ void __launch_bounds__(256) gemm1_kernel(const float* __restrict__ z) {
    __shared__ __align__(16) float As[16][68];
    __shared__ __align__(16) float Bs[16][68];

    int tid = threadIdx.x;
    int tx = tid & 15, ty = tid >> 4;
    int m0 = blockIdx.y * 64, n0 = blockIdx.x * 64;

    int a_row = tid & 63;
    int a_k4  = (tid >> 6) * 4;
    int b_k   = tid >> 4;
    int b_n4  = (tid & 15) * 4;

    const float* Ap = z + (size_t)(m0 + a_row) * D_N + a_k4;
    const float* Bp = g_Afin + (size_t)b_k * AFIN_N + n0 + b_n4;

    unsigned long long acc[4][2];
#pragma unroll
    for (int i = 0; i < 4; i++) { acc[i][0] = 0ull; acc[i][1] = 0ull; }

    for (int k0 = 0; k0 < D_N; k0 += 16) {
        float4 av = *(const float4*)(Ap + k0);
        float4 mv = *(const float4*)(g_means + k0 + a_k4);
        float4 bv = *(const float4*)(Bp + (size_t)k0 * AFIN_N);
        av.x -= mv.x; av.y -= mv.y; av.z -= mv.z; av.w -= mv.w;
        __syncthreads();
        As[a_k4 + 0][a_row] = av.x;
        As[a_k4 + 1][a_row] = av.y;
        As[a_k4 + 2][a_row] = av.z;
        As[a_k4 + 3][a_row] = av.w;
        *(float4*)&Bs[b_k][b_n4] = bv;
        __syncthreads();
#pragma unroll
        for (int kk = 0; kk < 16; kk++) {
            float4 a = *(const float4*)&As[kk][ty * 4];
            ulonglong2 b = *(const ulonglong2*)&Bs[kk][tx * 4];
            unsigned long long a2[4];
            a2[0] = bcast2(a.x); a2[1] = bcast2(a.y);
            a2[2] = bcast2(a.z); a2[3] = bcast2(a.w);
#pragma unroll
            for (int i = 0; i < 4; i++) {
                fma2(acc[i][0], a2[i], b.x);
                fma2(acc[i][1], a2[i], b.y);
            }
        }
    }
#pragma unroll
    for (int jp = 0; jp < 2; jp++) {
        int ne = n0 + tx * 4 + 2 * jp;
#pragma unroll
        for (int i = 0; i < 4; i++) {
            float2 p = unpk2(acc[i][jp]);
            int m = m0 + ty * 4 + i;
            g_u2t[(size_t)ne * B_N + m]       = p.x;
            g_u2t[(size_t)(ne + 1) * B_N + m] = p.y;
        }
    }
}

/* ------------------------------------------------------------------ */
/* ECF slice loss: ONE WARP PER DIRECTION (no smem, no block sync)    */
/* ------------------------------------------------------------------ */
__device__ __forceinline__ void ecf_sample(float x, float ar[8], float ai[8]) {
    float s1, c1;
    __sincosf(x, &s1, &c1);
    float twoc = c1 + c1;
    float cm = 1.f, sm = 0.f;
    float c = c1, s = s1;
#pragma unroll
    for (int j = 0; j < 8; j++) {
        ar[j] += c; ai[j] += s;
        float cn = fmaf(twoc, c, -cm);
        float sn = fmaf(twoc, s, -sm);
        cm = c; sm = s; c = cn; s = sn;
    }
}

__global__ void __launch_bounds__(256) ecf_kernel(int which) {
    const float*  __restrict__ ut = which ? g_u2t : g_ut;
    double*       __restrict__ L  = which ? g_floss : g_losses;
    int warp = threadIdx.x >> 5, lane = threadIdx.x & 31;
    int a = blockIdx.x * 8 + warp;
    const float4* row4 = (const float4*)(ut + (size_t)a * B_N);

    float ar[8], ai[8];
#pragma unroll
    for (int j = 0; j < 8; j++) { ar[j] = 0.f; ai[j] = 0.f; }

#pragma unroll 4
    for (int it = 0; it < 16; it++) {
        float4 xv = row4[lane + 32 * it];
        ecf_sample(0.625f * xv.x, ar, ai);
        ecf_sample(0.625f * xv.y, ar, ai);
        ecf_sample(0.625f * xv.z, ar, ai);
        ecf_sample(0.625f * xv.w, ar, ai);
    }

    float q[16];
#pragma unroll
    for (int k = 0; k < 16; k++) {
        float v = (k < 8) ? ar[k] : ai[k - 8];
#pragma unroll
        for (int o = 16; o; o >>= 1) v += __shfl_xor_sync(0xffffffffu, v, o);
        q[k] = v;
    }

    if (lane == 0) {
        const double invB = 1.0 / 2048.0;
        double loss = 0.0;
#pragma unroll
        for (int j = 1; j <= 8; j++) {
            double tj = 0.625 * (double)j;
            double ph = exp(-0.5 * tj * tj);
            double re = (double)q[j - 1] * invB - ph;
            double im = (double)q[8 + j - 1] * invB;
            double integ = (re * re + im * im) * ph;
            loss += ((j == 8) ? 0.625 : 1.25) * integ;
        }
        L[a] = loss;
    }
}

/* ------------------------------------------------------------------ */
/* Bitonic sort                                                       */
/* ------------------------------------------------------------------ */
__global__ void __launch_bounds__(1024) sort_kernel() {
    __shared__ long long sv[2048];
    __shared__ int       si[2048];
    int t = threadIdx.x;
    for (int i = t; i < 2048; i += 1024) {
        sv[i] = __double_as_longlong(g_losses[i]);
        si[i] = i;
    }
    __syncthreads();
    for (int k = 2; k <= 2048; k <<= 1) {
        for (int jj = k >> 1; jj > 0; jj >>= 1) {
            for (int i = t; i < 2048; i += 1024) {
                int ixj = i ^ jj;
                if (ixj > i) {
                    long long va = sv[i], vb = sv[ixj];
                    int       ia = si[i], ib = si[ixj];
                    bool aFirst = (va > vb) || (va == vb && ia < ib);
                    bool dirAsc = ((i & k) == 0);
                    if (aFirst != dirAsc) {
                        sv[i] = vb; sv[ixj] = va;
                        si[i] = ib; si[ixj] = ia;
                    }
                }
            }
            __syncthreads();
        }
    }
    for (int i = t; i < HARD_N; i += 1024) g_ranked[i] = si[i];
}

/* ------------------------------------------------------------------ */
/* GS via Cholesky                                                    */
/* ------------------------------------------------------------------ */
__global__ void gather_kernel() {
    int idx = blockIdx.x * 256 + threadIdx.x;
    int i = idx >> 10, d = idx & 1023;
    g_H[idx] = g_Apool[(size_t)d * POOL_N + g_ranked[i]];
}

__global__ void __launch_bounds__(256) syrk_kernel() {
    int i = blockIdx.x;
    __shared__ float hi[D_N];
    int tid = threadIdx.x;
    *(float4*)&hi[tid * 4] = *(const float4*)&g_H[(size_t)i * D_N + tid * 4];
    __syncthreads();
    int lane = tid & 31, warp = tid >> 5;
    const float4* hi4 = (const float4*)hi;
    for (int j = warp; j < HARD_N; j += 8) {
        const float4* hj = (const float4*)&g_H[(size_t)j * D_N];
        float acc = 0.f;
        for (int d4 = lane; d4 < 256; d4 += 32) {
            float4 a = hi4[d4];
            float4 b = hj[d4];
            acc = fmaf(a.x, b.x, fmaf(a.y, b.y, fmaf(a.z, b.z, fmaf(a.w, b.w, acc))));
        }
#pragma unroll
        for (int o = 16; o; o >>= 1) acc += __shfl_down_sync(0xffffffffu, acc, o);
        if (lane == 0) g_G[i * HARD_N + j] = acc;
    }
}

/* (128,4) threads: q = k-quarter split, smem partial combine         */
__global__ void __launch_bounds__(512) cholinv_kernel() {
    extern __shared__ float sbuf[];
    float* sR = sbuf;                          /* 128*128 */
    float* sT = sbuf + HARD_N * HARD_N;        /* 128*128 */
    float* sp = sbuf + 2 * HARD_N * HARD_N;    /* 4*128   */
    __shared__ float sdiag;
    int m = threadIdx.x;     /* 0..127 */
    int q = threadIdx.y;     /* 0..3   */

    for (int k = q * 32; k < q * 32 + 32; k++) {
        sR[k * HARD_N + m] = g_G[k * HARD_N + m];
        sT[k * HARD_N + m] = 0.f;
    }
    __syncthreads();

    /* Cholesky: G = R^T R, row j at step j */
    for (int j = 0; j < HARD_N; j++) {
        int k0 = q * 32;
        int k1 = (j < k0 + 32) ? ((j > k0) ? j : k0) : (k0 + 32);
        float s[4] = {0.f, 0.f, 0.f, 0.f};
        int k = k0;
        for (; k + 4 <= k1; k += 4) {
#pragma unroll
            for (int u = 0; u < 4; u++)
                s[u] = fmaf(sR[(k + u) * HARD_N + j], sR[(k + u) * HARD_N + m], s[u]);
        }
        for (int u = 0; k < k1; k++, u++)
            s[u] = fmaf(sR[k * HARD_N + j], sR[k * HARD_N + m], s[u]);
        sp[q * HARD_N + m] = (s[0] + s[1]) + (s[2] + s[3]);
        __syncthreads();

        float smm = 0.f;
        if (q == 0) {
            smm = (sp[m] + sp[HARD_N + m]) + (sp[2 * HARD_N + m] + sp[3 * HARD_N + m]);
            if (m == j) {
                float dd = sR[j * HARD_N + j] - smm;
                sdiag = fmaxf(sqrtf(fmaxf(dd, 0.f)), 1e-12f);
            }
        }
        __syncthreads();
        if (q == 0) {
            float rjj = sdiag;
            if (m > j)       sR[j * HARD_N + m] = (sR[j * HARD_N + m] - smm) / rjj;
            else if (m == j) sR[j * HARD_N + j] = rjj;
        }
        __syncthreads();
    }

    /* T = R^{-1}: column m, k-quarter q */
    if (q == 0) sT[m * HARD_N + m] = 1.f / sR[m * HARD_N + m];
    __syncthreads();
    for (int i = HARD_N - 2; i >= 0; i--) {
        int k0 = (i + 1 > q * 32) ? (i + 1) : (q * 32);
        int k1 = q * 32 + 32;
        float s0 = 0.f, s1 = 0.f;
        int k = k0;
        for (; k + 2 <= k1; k += 2) {
            s0 = fmaf(sR[i * HARD_N + k],     sT[k * HARD_N + m],       s0);
            s1 = fmaf(sR[i * HARD_N + k + 1], sT[(k + 1) * HARD_N + m], s1);
        }
        if (k < k1) s0 = fmaf(sR[i * HARD_N + k], sT[k * HARD_N + m], s0);
        sp[q * HARD_N + m] = s0 + s1;
        __syncthreads();
        if (q == 0 && i < m) {
            float tot = (sp[m] + sp[HARD_N + m]) + (sp[2 * HARD_N + m] + sp[3 * HARD_N + m]);
            sT[i * HARD_N + m] = -tot / sR[i * HARD_N + i];
        }
        __syncthreads();
    }

    for (int k = q * 32; k < q * 32 + 32; k++)
        g_T[k * HARD_N + m] = sT[k * HARD_N + m];
}

__global__ void __launch_bounds__(256) qht_kernel() {
    int j = threadIdx.x & 127;
    int d = blockIdx.x * 2 + (threadIdx.x >> 7);
    float a0 = 0.f, a1 = 0.f;
    for (int k = 0; k < HARD_N; k += 2) {
        float h0 = g_H[(size_t)k * D_N + d];
        float h1 = g_H[(size_t)(k + 1) * D_N + d];
        a0 = fmaf(h0, g_T[k * HARD_N + j], a0);
        a1 = fmaf(h1, g_T[(k + 1) * HARD_N + j], a1);
    }
    g_Q[(size_t)j * D_N + d] = a0 + a1;
}

/* ------------------------------------------------------------------ */
/* Extra directions                                                   */
/* ------------------------------------------------------------------ */
__global__ void qtr_kernel() {
    __shared__ float sm[4][64];
    int i = blockIdx.x;
    int j = threadIdx.x, dq = threadIdx.y;
    const float* qp = g_Q + (size_t)i * D_N + dq * 256;
    const float* r = g_R + (size_t)(dq * 256) * EXTRA_N + j;
    float s = 0.f;
#pragma unroll 4
    for (int d = 0; d < 256; d++)
        s = fmaf(qp[d], r[(size_t)d * EXTRA_N], s);
    sm[dq][j] = s;
    __syncthreads();
    if (dq == 0) {
        double t = (double)sm[0][j] + (double)sm[1][j]
                 + (double)sm[2][j] + (double)sm[3][j];
        g_C[i * EXTRA_N + j] = (float)t;
    }
}

__global__ void subproj_kernel() {
    int idx = blockIdx.x * blockDim.x + threadIdx.x;
    int d = idx >> 6, j = idx & 63;
    float s = 0.f;
    for (int i = 0; i < HARD_N; i++)
        s = fmaf(g_Q[(size_t)i * D_N + d], g_C[i * EXTRA_N + j], s);
    g_R[idx] -= s;
}

__global__ void assemble_kernel() {
    int idx = blockIdx.x * blockDim.x + threadIdx.x;
    int d = idx >> 8, c = idx & 255;
    float v = 0.f;
    if (c < HARD_N)      v = g_Q[(size_t)c * D_N + d];
    else if (c < NFIN)   v = g_R[(size_t)d * EXTRA_N + (c - HARD_N)];
    g_Afin[idx] = v;
}

__global__ void final_kernel(float* __restrict__ out) {
    __shared__ double sh[256];
    int t = threadIdx.x;
    sh[t] = (t < NFIN) ? g_floss[t] : 0.0;
    __syncthreads();
    if (t == 0) {
        double s = 0.0;
        for (int i = 0; i < NFIN; i++) s += sh[i];
        out[0] = (float)((s / 192.0) * 2048.0);
    }
}

/* ------------------------------------------------------------------ */
extern "C" void kernel_launch(void* const* d_in, const int* in_sizes, int n_in,
                              void* d_out, int out_size) {
    const float* z; const int* seed;
    if (in_sizes[0] == 1) { seed = (const int*)d_in[0]; z = (const float*)d_in[1]; }
    else                  { z = (const float*)d_in[0]; seed = (const int*)d_in[1]; }
    float* out = (float*)d_out;

    const int chol_smem = (2 * HARD_N * HARD_N + 4 * HARD_N) * (int)sizeof(float);
    static int smem_set = 0;
    if (!smem_set) {
        cudaFuncSetAttribute(cholinv_kernel,
                             cudaFuncAttributeMaxDynamicSharedMemorySize,
                             chol_smem);
        smem_set = 1;
    }

    setup_kernel<<<SETUP_POOL_BLKS + SETUP_CM_BLKS + SETUP_EXTRA_BLKS, 256>>>(z, seed);
    norm_comb_kernel<<<33, dim3(64, 16)>>>();

    gemm0_kernel<<<dim3(POOL_N / BN, B_N / BM), 512>>>(z);
    ecf_kernel<<<POOL_N / 8, 256>>>(0);

    sort_kernel<<<1, 1024>>>();

    gather_kernel<<<(HARD_N * D_N) / 256, 256>>>();
    syrk_kernel<<<HARD_N, 256>>>();
    cholinv_kernel<<<1, dim3(128, 4), chol_smem>>>();
    qht_kernel<<<D_N / 2, 256>>>();

    qtr_kernel<<<HARD_N, dim3(64, 4)>>>();
    subproj_kernel<<<(D_N * EXTRA_N) / 256, 256>>>();
    norm_cols_kernel<<<1, dim3(64, 16)>>>(1);

    assemble_kernel<<<(D_N * AFIN_N) / 256, 256>>>();
    gemm1_kernel<<<dim3(NFIN / 64, B_N / 64), 256>>>(z);
    ecf_kernel<<<NFIN / 8, 256>>>(1);

    final_kernel<<<1, 256>>>(out);
}

// round 15
// speedup vs baseline: 1.0565x; 1.0565x over previous
#include <cuda_runtime.h>
#include <stdint.h>

#define B_N    2048
#define D_N    1024
#define POOL_N 2048
#define HARD_N 128
#define EXTRA_N 64
#define AFIN_N 256
#define NFIN   192

#define BM 128
#define BN 128

/* ------------------------------------------------------------------ */
/* Scratch                                                            */
/* ------------------------------------------------------------------ */
__device__ float  g_Apool[D_N * POOL_N];
__device__ float  g_means[D_N];
__device__ float  g_ut[POOL_N * B_N];
__device__ float  g_u2t[AFIN_N * B_N];
__device__ double g_losses[POOL_N];
__device__ int    g_ranked[HARD_N];
__device__ float  g_H[HARD_N * D_N];
__device__ float  g_G[HARD_N * HARD_N];
__device__ float  g_T[HARD_N * HARD_N];
__device__ float  g_Q[HARD_N * D_N];
__device__ float  g_R[D_N * EXTRA_N];
__device__ float  g_C[HARD_N * EXTRA_N];
__device__ float  g_Afin[D_N * AFIN_N];
__device__ double g_floss[NFIN];

/* ---------------- packed f32x2 helpers ---------------------------- */
__device__ __forceinline__ unsigned long long bcast2(float x) {
    unsigned long long r;
    asm("mov.b64 %0, {%1, %1};" : "=l"(r) : "f"(x));
    return r;
}
__device__ __forceinline__ void fma2(unsigned long long& d,
                                     unsigned long long a,
                                     unsigned long long b) {
    asm("fma.rn.f32x2 %0, %1, %2, %0;" : "+l"(d) : "l"(a), "l"(b));
}
__device__ __forceinline__ float2 unpk2(unsigned long long v) {
    float2 r;
    asm("mov.b64 {%0, %1}, %2;" : "=f"(r.x), "=f"(r.y) : "l"(v));
    return r;
}

/* ------------------------------------------------------------------ */
/* JAX threefry2x32 (partitionable)                                   */
/* ------------------------------------------------------------------ */
__device__ __forceinline__ uint32_t rotl32(uint32_t x, int r) {
    return (x << r) | (x >> (32 - r));
}
__device__ __forceinline__ void threefry2x32(uint32_t k0, uint32_t k1,
                                             uint32_t x0, uint32_t x1,
                                             uint32_t& o0, uint32_t& o1) {
    uint32_t ks2 = k0 ^ k1 ^ 0x1BD11BDAu;
    x0 += k0; x1 += k1;
#define TFR(r) { x0 += x1; x1 = rotl32(x1, (r)); x1 ^= x0; }
    TFR(13) TFR(15) TFR(26) TFR(6)  x0 += k1;  x1 += ks2 + 1u;
    TFR(17) TFR(29) TFR(16) TFR(24) x0 += ks2; x1 += k0  + 2u;
    TFR(13) TFR(15) TFR(26) TFR(6)  x0 += k0;  x1 += k1  + 3u;
    TFR(17) TFR(29) TFR(16) TFR(24) x0 += k1;  x1 += ks2 + 4u;
    TFR(13) TFR(15) TFR(26) TFR(6)  x0 += ks2; x1 += k0  + 5u;
#undef TFR
    o0 = x0; o1 = x1;
}
__device__ __forceinline__ float erfinv_xla(float x) {
    float w = -log1pf(-x * x);
    float p;
    if (w < 5.0f) {
        w -= 2.5f;
        p = 2.81022636e-08f;
        p = fmaf(p, w, 3.43273939e-07f);
        p = fmaf(p, w, -3.5233877e-06f);
        p = fmaf(p, w, -4.39150654e-06f);
        p = fmaf(p, w, 0.00021858087f);
        p = fmaf(p, w, -0.00125372503f);
        p = fmaf(p, w, -0.00417768164f);
        p = fmaf(p, w, 0.246640727f);
        p = fmaf(p, w, 1.50140941f);
    } else {
        w = sqrtf(w) - 3.0f;
        p = -0.000200214257f;
        p = fmaf(p, w, 0.000100950558f);
        p = fmaf(p, w, 0.00134934322f);
        p = fmaf(p, w, -0.00367342844f);
        p = fmaf(p, w, 0.00573950773f);
        p = fmaf(p, w, -0.0076224613f);
        p = fmaf(p, w, 0.00943887047f);
        p = fmaf(p, w, 1.00167406f);
        p = fmaf(p, w, 2.83297682f);
    }
    return p * x;
}
__device__ __forceinline__ float bits_to_normal(uint32_t b) {
    float f = __uint_as_float((b >> 9) | 0x3f800000u) - 1.0f;
    const float minv = -0.99999994f;
    float u = fmaf(f, 2.0f, minv);
    u = fmaxf(u, minv);
    return 1.41421356f * erfinv_xla(u);
}

/* ------------------------------------------------------------------ */
/* Fused setup: pool gen, colmean, extra gen                          */
/* ------------------------------------------------------------------ */
#define SETUP_POOL_BLKS  (D_N * POOL_N / 256)
#define SETUP_CM_BLKS    16
#define SETUP_EXTRA_BLKS (D_N * EXTRA_N / 256)

__global__ void __launch_bounds__(256) setup_kernel(const float* __restrict__ z,
                                                    const int* __restrict__ seed_ptr) {
    int b = blockIdx.x;
    if (b < SETUP_POOL_BLKS) {
        int i = b * 256 + threadIdx.x;
        uint32_t k1 = (uint32_t)seed_ptr[0];
        uint32_t o0, o1;
        threefry2x32(0u, k1, 0u, (uint32_t)i, o0, o1);
        g_Apool[i] = bits_to_normal(o0 ^ o1);
    } else if (b < SETUP_POOL_BLKS + SETUP_CM_BLKS) {
        __shared__ float2 sm[4][64];
        int xb = b - SETUP_POOL_BLKS;
        int x = threadIdx.x & 63, y = threadIdx.x >> 6;
        int c = xb * 64 + x;
        float s = 0.f, comp = 0.f;
        for (int r = y; r < B_N; r += 4) {
            float v = z[(size_t)r * D_N + c];
            float yv = v - comp;
            float t = s + yv;
            comp = (t - s) - yv;
            s = t;
        }
        sm[y][x] = make_float2(s, comp);
        __syncthreads();
        if (y == 0) {
            double tot = 0.0;
            for (int w = 0; w < 4; w++) {
                float2 p = sm[w][x];
                tot += (double)p.x - (double)p.y;
            }
            g_means[c] = (float)(tot * (1.0 / 2048.0));
        }
    } else {
        int i = (b - SETUP_POOL_BLKS - SETUP_CM_BLKS) * 256 + threadIdx.x;
        uint32_t k1 = (uint32_t)(seed_ptr[0] + 9991);
        uint32_t o0, o1;
        threefry2x32(0u, k1, 0u, (uint32_t)i, o0, o1);
        g_R[i] = bits_to_normal(o0 ^ o1);
    }
}

/* ------------------------------------------------------------------ */
/* Column normalize                                                   */
/* ------------------------------------------------------------------ */
__device__ __forceinline__ void norm_cols_body(float* A, int nc, int col) {
    __shared__ float2 sm[16][64];
    __shared__ float sden[64];
    int x = threadIdx.x, y = threadIdx.y;
    float s = 0.f, comp = 0.f;
    for (int r = 0; r < 64; r++) {
        int d = y * 64 + r;
        float v = A[(size_t)d * nc + col];
        float v2 = v * v;
        float yv = v2 - comp;
        float t = s + yv;
        comp = (t - s) - yv;
        s = t;
    }
    sm[y][x] = make_float2(s, comp);
    __syncthreads();
    if (y == 0) {
        double tot = 0.0;
        for (int w = 0; w < 16; w++) {
            float2 p = sm[w][x];
            tot += (double)p.x - (double)p.y;
        }
        sden[x] = (float)sqrt(tot) + 1e-12f;
    }
    __syncthreads();
    float den = sden[x];
    for (int r = 0; r < 64; r++) {
        int d = y * 64 + r;
        A[(size_t)d * nc + col] /= den;
    }
}

__global__ void norm_comb_kernel() {
    if (blockIdx.x < 32)
        norm_cols_body(g_Apool, POOL_N, blockIdx.x * 64 + threadIdx.x);
    else
        norm_cols_body(g_R, EXTRA_N, threadIdx.x);
}

__global__ void norm_cols_kernel(int which) {
    float* A = which ? g_R : g_Apool;
    int nc   = which ? EXTRA_N : POOL_N;
    norm_cols_body(A, nc, blockIdx.x * 64 + threadIdx.x);
}

/* ------------------------------------------------------------------ */
/* GEMM0: 128x128 tile, 256 thr, 2 CTAs/SM, f32x2, double-buffered    */
/* Same per-element FMA order as the 512-thread version -> u bitwise  */
/* ------------------------------------------------------------------ */
__global__ void __launch_bounds__(256, 2) gemm0_kernel(const float* __restrict__ z) {
    __shared__ __align__(16) float As[2][8][BM + 4];
    __shared__ __align__(16) float Bs[2][8][BN + 4];

    int tid = threadIdx.x;
    int tx = tid & 15;            /* 16 x 8n = 128 n */
    int ty = tid >> 4;            /* 16 x 8m = 128 m */
    int m0 = blockIdx.y * BM, n0 = blockIdx.x * BN;

    int a_row = tid >> 1;         /* 0..127 */
    int a_k4  = (tid & 1) * 4;
    int b_k   = tid >> 5;         /* 0..7   */
    int b_n4  = (tid & 31) * 4;   /* 0..124 */

    const float* Ap = z + (size_t)(m0 + a_row) * D_N + a_k4;
    const float* Bp = g_Apool + (size_t)b_k * POOL_N + n0 + b_n4;

    unsigned long long acc[8][4];
#pragma unroll
    for (int i = 0; i < 8; i++)
#pragma unroll
        for (int jp = 0; jp < 4; jp++) acc[i][jp] = 0ull;

    float4 av = *(const float4*)Ap;
    float4 mv = *(const float4*)(g_means + a_k4);
    float4 bv = *(const float4*)Bp;

    for (int c = 0; c < D_N / 8; c++) {
        int buf = c & 1;
        As[buf][a_k4 + 0][a_row] = av.x - mv.x;
        As[buf][a_k4 + 1][a_row] = av.y - mv.y;
        As[buf][a_k4 + 2][a_row] = av.z - mv.z;
        As[buf][a_k4 + 3][a_row] = av.w - mv.w;
        *(float4*)&Bs[buf][b_k][b_n4] = bv;
        __syncthreads();
        if (c + 1 < D_N / 8) {
            int k0 = (c + 1) * 8;
            av = *(const float4*)(Ap + k0);
            mv = *(const float4*)(g_means + k0 + a_k4);
            bv = *(const float4*)(Bp + (size_t)k0 * POOL_N);
        }
#pragma unroll
        for (int kk = 0; kk < 8; kk++) {
            float4 a0 = *(const float4*)&As[buf][kk][ty * 8];
            float4 a1 = *(const float4*)&As[buf][kk][ty * 8 + 4];
            ulonglong2 b0 = *(const ulonglong2*)&Bs[buf][kk][tx * 8];
            ulonglong2 b1 = *(const ulonglong2*)&Bs[buf][kk][tx * 8 + 4];
            unsigned long long a2[8];
            a2[0] = bcast2(a0.x); a2[1] = bcast2(a0.y);
            a2[2] = bcast2(a0.z); a2[3] = bcast2(a0.w);
            a2[4] = bcast2(a1.x); a2[5] = bcast2(a1.y);
            a2[6] = bcast2(a1.z); a2[7] = bcast2(a1.w);
#pragma unroll
            for (int i = 0; i < 8; i++) {
                fma2(acc[i][0], a2[i], b0.x);
                fma2(acc[i][1], a2[i], b0.y);
                fma2(acc[i][2], a2[i], b1.x);
                fma2(acc[i][3], a2[i], b1.y);
            }
        }
    }

#pragma unroll
    for (int jp = 0; jp < 4; jp++) {
        float lo[8], hi[8];
#pragma unroll
        for (int i = 0; i < 8; i++) {
            float2 p = unpk2(acc[i][jp]);
            lo[i] = p.x; hi[i] = p.y;
        }
        int ne = n0 + tx * 8 + 2 * jp;
        float* be = &g_ut[(size_t)ne * B_N + m0 + ty * 8];
        float* bo = &g_ut[(size_t)(ne + 1) * B_N + m0 + ty * 8];
        *(float4*)be       = make_float4(lo[0], lo[1], lo[2], lo[3]);
        *(float4*)(be + 4) = make_float4(lo[4], lo[5], lo[6], lo[7]);
        *(float4*)bo       = make_float4(hi[0], hi[1], hi[2], hi[3]);
        *(float4*)(bo + 4) = make_float4(hi[4], hi[5], hi[6], hi[7]);
    }
}

/* ------------------------------------------------------------------ */
/* GEMM1 (final): 64x64 tiles, f32x2                                  */
/* ------------------------------------------------------------------ */
__global__ void __launch_bounds__(256) gemm1_kernel(const float* __restrict__ z) {
    __shared__ __align__(16) float As[16][68];
    __shared__ __align__(16) float Bs[16][68];

    int tid = threadIdx.x;
    int tx = tid & 15, ty = tid >> 4;
    int m0 = blockIdx.y * 64, n0 = blockIdx.x * 64;

    int a_row = tid & 63;
    int a_k4  = (tid >> 6) * 4;
    int b_k   = tid >> 4;
    int b_n4  = (tid & 15) * 4;

    const float* Ap = z + (size_t)(m0 + a_row) * D_N + a_k4;
    const float* Bp = g_Afin + (size_t)b_k * AFIN_N + n0 + b_n4;

    unsigned long long acc[4][2];
#pragma unroll
    for (int i = 0; i < 4; i++) { acc[i][0] = 0ull; acc[i][1] = 0ull; }

    for (int k0 = 0; k0 < D_N; k0 += 16) {
        float4 av = *(const float4*)(Ap + k0);
        float4 mv = *(const float4*)(g_means + k0 + a_k4);
        float4 bv = *(const float4*)(Bp + (size_t)k0 * AFIN_N);
        av.x -= mv.x; av.y -= mv.y; av.z -= mv.z; av.w -= mv.w;
        __syncthreads();
        As[a_k4 + 0][a_row] = av.x;
        As[a_k4 + 1][a_row] = av.y;
        As[a_k4 + 2][a_row] = av.z;
        As[a_k4 + 3][a_row] = av.w;
        *(float4*)&Bs[b_k][b_n4] = bv;
        __syncthreads();
#pragma unroll
        for (int kk = 0; kk < 16; kk++) {
            float4 a = *(const float4*)&As[kk][ty * 4];
            ulonglong2 b = *(const ulonglong2*)&Bs[kk][tx * 4];
            unsigned long long a2[4];
            a2[0] = bcast2(a.x); a2[1] = bcast2(a.y);
            a2[2] = bcast2(a.z); a2[3] = bcast2(a.w);
#pragma unroll
            for (int i = 0; i < 4; i++) {
                fma2(acc[i][0], a2[i], b.x);
                fma2(acc[i][1], a2[i], b.y);
            }
        }
    }
#pragma unroll
    for (int jp = 0; jp < 2; jp++) {
        int ne = n0 + tx * 4 + 2 * jp;
#pragma unroll
        for (int i = 0; i < 4; i++) {
            float2 p = unpk2(acc[i][jp]);
            int m = m0 + ty * 4 + i;
            g_u2t[(size_t)ne * B_N + m]       = p.x;
            g_u2t[(size_t)(ne + 1) * B_N + m] = p.y;
        }
    }
}

/* ------------------------------------------------------------------ */
/* ECF slice loss (R13 version: block/direction, plain f32 butterfly) */
/* ------------------------------------------------------------------ */
__device__ __forceinline__ void ecf_sample(float x, float ar[8], float ai[8]) {
    float s1, c1;
    __sincosf(x, &s1, &c1);
    float twoc = c1 + c1;
    float cm = 1.f, sm = 0.f;
    float c = c1, s = s1;
#pragma unroll
    for (int j = 0; j < 8; j++) {
        ar[j] += c; ai[j] += s;
        float cn = fmaf(twoc, c, -cm);
        float sn = fmaf(twoc, s, -sm);
        cm = c; sm = s; c = cn; s = sn;
    }
}

__global__ void __launch_bounds__(256) ecf_kernel(int which) {
    const float*  __restrict__ ut = which ? g_u2t : g_ut;
    double*       __restrict__ L  = which ? g_floss : g_losses;
    int a = blockIdx.x;
    int t = threadIdx.x;
    int lane = t & 31, warp = t >> 5;
    const float4* row4 = (const float4*)(ut + (size_t)a * B_N);

    float ar[8], ai[8];
#pragma unroll
    for (int j = 0; j < 8; j++) { ar[j] = 0.f; ai[j] = 0.f; }

#pragma unroll
    for (int it = 0; it < 2; it++) {
        float4 xv = row4[t + 256 * it];
        ecf_sample(0.625f * xv.x, ar, ai);
        ecf_sample(0.625f * xv.y, ar, ai);
        ecf_sample(0.625f * xv.z, ar, ai);
        ecf_sample(0.625f * xv.w, ar, ai);
    }

    __shared__ float sred[8][16];
    __shared__ double sredd[16];
#pragma unroll
    for (int q = 0; q < 16; q++) {
        float v = (q < 8) ? ar[q] : ai[q - 8];
#pragma unroll
        for (int o = 16; o; o >>= 1) v += __shfl_xor_sync(0xffffffffu, v, o);
        if (lane == 0) sred[warp][q] = v;
    }
    __syncthreads();
    if (t < 16) {
        double tot = 0.0;
        for (int w = 0; w < 8; w++) tot += (double)sred[w][t];
        sredd[t] = tot;
    }
    __syncthreads();
    if (t == 0) {
        const double invB = 1.0 / 2048.0;
        double loss = 0.0;
#pragma unroll
        for (int j = 1; j <= 8; j++) {
            double tj = 0.625 * (double)j;
            double ph = exp(-0.5 * tj * tj);
            double re = sredd[j - 1] * invB - ph;
            double im = sredd[8 + j - 1] * invB;
            double integ = (re * re + im * im) * ph;
            loss += ((j == 8) ? 0.625 : 1.25) * integ;
        }
        L[a] = loss;
    }
}

/* ------------------------------------------------------------------ */
/* Bitonic sort                                                       */
/* ------------------------------------------------------------------ */
__global__ void __launch_bounds__(1024) sort_kernel() {
    __shared__ long long sv[2048];
    __shared__ int       si[2048];
    int t = threadIdx.x;
    for (int i = t; i < 2048; i += 1024) {
        sv[i] = __double_as_longlong(g_losses[i]);
        si[i] = i;
    }
    __syncthreads();
    for (int k = 2; k <= 2048; k <<= 1) {
        for (int jj = k >> 1; jj > 0; jj >>= 1) {
            for (int i = t; i < 2048; i += 1024) {
                int ixj = i ^ jj;
                if (ixj > i) {
                    long long va = sv[i], vb = sv[ixj];
                    int       ia = si[i], ib = si[ixj];
                    bool aFirst = (va > vb) || (va == vb && ia < ib);
                    bool dirAsc = ((i & k) == 0);
                    if (aFirst != dirAsc) {
                        sv[i] = vb; sv[ixj] = va;
                        si[i] = ib; si[ixj] = ia;
                    }
                }
            }
            __syncthreads();
        }
    }
    for (int i = t; i < HARD_N; i += 1024) g_ranked[i] = si[i];
}

/* ------------------------------------------------------------------ */
/* GS via Cholesky (R13 single-block 128-thread version)              */
/* ------------------------------------------------------------------ */
__global__ void gather_kernel() {
    int idx = blockIdx.x * 256 + threadIdx.x;
    int i = idx >> 10, d = idx & 1023;
    g_H[idx] = g_Apool[(size_t)d * POOL_N + g_ranked[i]];
}

__global__ void __launch_bounds__(256) syrk_kernel() {
    int i = blockIdx.x;
    __shared__ float hi[D_N];
    int tid = threadIdx.x;
    *(float4*)&hi[tid * 4] = *(const float4*)&g_H[(size_t)i * D_N + tid * 4];
    __syncthreads();
    int lane = tid & 31, warp = tid >> 5;
    const float4* hi4 = (const float4*)hi;
    for (int j = warp; j < HARD_N; j += 8) {
        const float4* hj = (const float4*)&g_H[(size_t)j * D_N];
        float acc = 0.f;
        for (int d4 = lane; d4 < 256; d4 += 32) {
            float4 a = hi4[d4];
            float4 b = hj[d4];
            acc = fmaf(a.x, b.x, fmaf(a.y, b.y, fmaf(a.z, b.z, fmaf(a.w, b.w, acc))));
        }
#pragma unroll
        for (int o = 16; o; o >>= 1) acc += __shfl_down_sync(0xffffffffu, acc, o);
        if (lane == 0) g_G[i * HARD_N + j] = acc;
    }
}

__global__ void __launch_bounds__(128) cholinv_kernel() {
    extern __shared__ float sbuf[];
    float* sR = sbuf;
    float* sT = sbuf + HARD_N * HARD_N;
    int m = threadIdx.x;
    __shared__ float sdiag;

    for (int k = 0; k < HARD_N; k++) {
        sR[k * HARD_N + m] = g_G[k * HARD_N + m];
        sT[k * HARD_N + m] = 0.f;
    }
    __syncthreads();

    for (int j = 0; j < HARD_N; j++) {
        float s[8];
#pragma unroll
        for (int u = 0; u < 8; u++) s[u] = 0.f;
        int k = 0;
        for (; k + 8 <= j; k += 8) {
#pragma unroll
            for (int u = 0; u < 8; u++)
                s[u] = fmaf(sR[(k + u) * HARD_N + j], sR[(k + u) * HARD_N + m], s[u]);
        }
        for (int u = 0; k < j; k++, u++)
            s[u] = fmaf(sR[k * HARD_N + j], sR[k * HARD_N + m], s[u]);
        float smm = ((s[0] + s[1]) + (s[2] + s[3])) + ((s[4] + s[5]) + (s[6] + s[7]));
        if (m == j) {
            float dd = sR[j * HARD_N + j] - smm;
            float r  = sqrtf(fmaxf(dd, 0.f));
            sdiag = fmaxf(r, 1e-12f);
        }
        __syncthreads();
        float rjj = sdiag;
        if (m > j)       sR[j * HARD_N + m] = (sR[j * HARD_N + m] - smm) / rjj;
        else if (m == j) sR[j * HARD_N + j] = rjj;
        __syncthreads();
    }

    int jc = m;
    sT[jc * HARD_N + jc] = 1.f / sR[jc * HARD_N + jc];
    for (int i = HARD_N - 2; i >= 0; i--) {
        float a[4];
#pragma unroll
        for (int u = 0; u < 4; u++) a[u] = 0.f;
        int k = i + 1;
        for (; k + 4 <= HARD_N; k += 4) {
#pragma unroll
            for (int u = 0; u < 4; u++)
                a[u] = fmaf(sR[i * HARD_N + k + u], sT[(k + u) * HARD_N + jc], a[u]);
        }
        for (int u = 0; k < HARD_N; k++, u++)
            a[u] = fmaf(sR[i * HARD_N + k], sT[k * HARD_N + jc], a[u]);
        float tot = (a[0] + a[1]) + (a[2] + a[3]);
        if (i < jc) sT[i * HARD_N + jc] = -tot / sR[i * HARD_N + i];
    }
    __syncthreads();
    for (int k = 0; k < HARD_N; k++)
        g_T[k * HARD_N + m] = sT[k * HARD_N + m];
}

__global__ void __launch_bounds__(256) qht_kernel() {
    int j = threadIdx.x & 127;
    int d = blockIdx.x * 2 + (threadIdx.x >> 7);
    float a0 = 0.f, a1 = 0.f;
    for (int k = 0; k < HARD_N; k += 2) {
        float h0 = g_H[(size_t)k * D_N + d];
        float h1 = g_H[(size_t)(k + 1) * D_N + d];
        a0 = fmaf(h0, g_T[k * HARD_N + j], a0);
        a1 = fmaf(h1, g_T[(k + 1) * HARD_N + j], a1);
    }
    g_Q[(size_t)j * D_N + d] = a0 + a1;
}

/* ------------------------------------------------------------------ */
/* Extra directions                                                   */
/* ------------------------------------------------------------------ */
__global__ void qtr_kernel() {
    __shared__ float sm[4][64];
    int i = blockIdx.x;
    int j = threadIdx.x, dq = threadIdx.y;
    const float* qp = g_Q + (size_t)i * D_N + dq * 256;
    const float* r = g_R + (size_t)(dq * 256) * EXTRA_N + j;
    float s = 0.f;
#pragma unroll 4
    for (int d = 0; d < 256; d++)
        s = fmaf(qp[d], r[(size_t)d * EXTRA_N], s);
    sm[dq][j] = s;
    __syncthreads();
    if (dq == 0) {
        double t = (double)sm[0][j] + (double)sm[1][j]
                 + (double)sm[2][j] + (double)sm[3][j];
        g_C[i * EXTRA_N + j] = (float)t;
    }
}

__global__ void subproj_kernel() {
    int idx = blockIdx.x * blockDim.x + threadIdx.x;
    int d = idx >> 6, j = idx & 63;
    float s = 0.f;
    for (int i = 0; i < HARD_N; i++)
        s = fmaf(g_Q[(size_t)i * D_N + d], g_C[i * EXTRA_N + j], s);
    g_R[idx] -= s;
}

__global__ void assemble_kernel() {
    int idx = blockIdx.x * blockDim.x + threadIdx.x;
    int d = idx >> 8, c = idx & 255;
    float v = 0.f;
    if (c < HARD_N)      v = g_Q[(size_t)c * D_N + d];
    else if (c < NFIN)   v = g_R[(size_t)d * EXTRA_N + (c - HARD_N)];
    g_Afin[idx] = v;
}

__global__ void final_kernel(float* __restrict__ out) {
    __shared__ double sh[256];
    int t = threadIdx.x;
    sh[t] = (t < NFIN) ? g_floss[t] : 0.0;
    __syncthreads();
    if (t == 0) {
        double s = 0.0;
        for (int i = 0; i < NFIN; i++) s += sh[i];
        out[0] = (float)((s / 192.0) * 2048.0);
    }
}

/* ------------------------------------------------------------------ */
extern "C" void kernel_launch(void* const* d_in, const int* in_sizes, int n_in,
                              void* d_out, int out_size) {
    const float* z; const int* seed;
    if (in_sizes[0] == 1) { seed = (const int*)d_in[0]; z = (const float*)d_in[1]; }
    else                  { z = (const float*)d_in[0]; seed = (const int*)d_in[1]; }
    float* out = (float*)d_out;

    static int smem_set = 0;
    if (!smem_set) {
        cudaFuncSetAttribute(cholinv_kernel,
                             cudaFuncAttributeMaxDynamicSharedMemorySize,
                             2 * HARD_N * HARD_N * (int)sizeof(float));
        smem_set = 1;
    }

    setup_kernel<<<SETUP_POOL_BLKS + SETUP_CM_BLKS + SETUP_EXTRA_BLKS, 256>>>(z, seed);
    norm_comb_kernel<<<33, dim3(64, 16)>>>();

    gemm0_kernel<<<dim3(POOL_N / BN, B_N / BM), 256>>>(z);
    ecf_kernel<<<POOL_N, 256>>>(0);

    sort_kernel<<<1, 1024>>>();

    gather_kernel<<<(HARD_N * D_N) / 256, 256>>>();
    syrk_kernel<<<HARD_N, 256>>>();
    cholinv_kernel<<<1, 128, 2 * HARD_N * HARD_N * sizeof(float)>>>();
    qht_kernel<<<D_N / 2, 256>>>();

    qtr_kernel<<<HARD_N, dim3(64, 4)>>>();
    subproj_kernel<<<(D_N * EXTRA_N) / 256, 256>>>();
    norm_cols_kernel<<<1, dim3(64, 16)>>>(1);

    assemble_kernel<<<(D_N * AFIN_N) / 256, 256>>>();
    gemm1_kernel<<<dim3(NFIN / 64, B_N / 64), 256>>>(z);
    ecf_kernel<<<NFIN, 256>>>(1);

    final_kernel<<<1, 256>>>(out);
}

// round 16
// speedup vs baseline: 1.0896x; 1.0313x over previous
#include <cuda_runtime.h>
#include <stdint.h>

#define B_N    2048
#define D_N    1024
#define POOL_N 2048
#define HARD_N 128
#define EXTRA_N 64
#define AFIN_N 256
#define NFIN   192

#define BM 128
#define BN 128

/* ------------------------------------------------------------------ */
/* Scratch                                                            */
/* ------------------------------------------------------------------ */
__device__ float  g_Apool[D_N * POOL_N];
__device__ float  g_means[D_N];
__device__ float  g_ut[POOL_N * B_N];
__device__ float  g_u2t[AFIN_N * B_N];
__device__ double g_losses[POOL_N];
__device__ int    g_ranked[HARD_N];
__device__ float  g_H[HARD_N * D_N];
__device__ float  g_G[HARD_N * HARD_N];   /* G, then overwritten by R */
__device__ float  g_T[HARD_N * HARD_N];
__device__ float  g_Q[HARD_N * D_N];
__device__ float  g_R[D_N * EXTRA_N];
__device__ float  g_C[HARD_N * EXTRA_N];
__device__ float  g_Afin[D_N * AFIN_N];
__device__ double g_floss[NFIN];

/* ---------------- packed f32x2 helpers ---------------------------- */
__device__ __forceinline__ unsigned long long bcast2(float x) {
    unsigned long long r;
    asm("mov.b64 %0, {%1, %1};" : "=l"(r) : "f"(x));
    return r;
}
__device__ __forceinline__ void fma2(unsigned long long& d,
                                     unsigned long long a,
                                     unsigned long long b) {
    asm("fma.rn.f32x2 %0, %1, %2, %0;" : "+l"(d) : "l"(a), "l"(b));
}
__device__ __forceinline__ float2 unpk2(unsigned long long v) {
    float2 r;
    asm("mov.b64 {%0, %1}, %2;" : "=f"(r.x), "=f"(r.y) : "l"(v));
    return r;
}

/* ------------------------------------------------------------------ */
/* JAX threefry2x32 (partitionable)                                   */
/* ------------------------------------------------------------------ */
__device__ __forceinline__ uint32_t rotl32(uint32_t x, int r) {
    return (x << r) | (x >> (32 - r));
}
__device__ __forceinline__ void threefry2x32(uint32_t k0, uint32_t k1,
                                             uint32_t x0, uint32_t x1,
                                             uint32_t& o0, uint32_t& o1) {
    uint32_t ks2 = k0 ^ k1 ^ 0x1BD11BDAu;
    x0 += k0; x1 += k1;
#define TFR(r) { x0 += x1; x1 = rotl32(x1, (r)); x1 ^= x0; }
    TFR(13) TFR(15) TFR(26) TFR(6)  x0 += k1;  x1 += ks2 + 1u;
    TFR(17) TFR(29) TFR(16) TFR(24) x0 += ks2; x1 += k0  + 2u;
    TFR(13) TFR(15) TFR(26) TFR(6)  x0 += k0;  x1 += k1  + 3u;
    TFR(17) TFR(29) TFR(16) TFR(24) x0 += k1;  x1 += ks2 + 4u;
    TFR(13) TFR(15) TFR(26) TFR(6)  x0 += ks2; x1 += k0  + 5u;
#undef TFR
    o0 = x0; o1 = x1;
}
__device__ __forceinline__ float erfinv_xla(float x) {
    float w = -log1pf(-x * x);
    float p;
    if (w < 5.0f) {
        w -= 2.5f;
        p = 2.81022636e-08f;
        p = fmaf(p, w, 3.43273939e-07f);
        p = fmaf(p, w, -3.5233877e-06f);
        p = fmaf(p, w, -4.39150654e-06f);
        p = fmaf(p, w, 0.00021858087f);
        p = fmaf(p, w, -0.00125372503f);
        p = fmaf(p, w, -0.00417768164f);
        p = fmaf(p, w, 0.246640727f);
        p = fmaf(p, w, 1.50140941f);
    } else {
        w = sqrtf(w) - 3.0f;
        p = -0.000200214257f;
        p = fmaf(p, w, 0.000100950558f);
        p = fmaf(p, w, 0.00134934322f);
        p = fmaf(p, w, -0.00367342844f);
        p = fmaf(p, w, 0.00573950773f);
        p = fmaf(p, w, -0.0076224613f);
        p = fmaf(p, w, 0.00943887047f);
        p = fmaf(p, w, 1.00167406f);
        p = fmaf(p, w, 2.83297682f);
    }
    return p * x;
}
__device__ __forceinline__ float bits_to_normal(uint32_t b) {
    float f = __uint_as_float((b >> 9) | 0x3f800000u) - 1.0f;
    const float minv = -0.99999994f;
    float u = fmaf(f, 2.0f, minv);
    u = fmaxf(u, minv);
    return 1.41421356f * erfinv_xla(u);
}

/* ------------------------------------------------------------------ */
/* Fused setup: pool gen, colmean, extra gen                          */
/* ------------------------------------------------------------------ */
#define SETUP_POOL_BLKS  (D_N * POOL_N / 256)
#define SETUP_CM_BLKS    16
#define SETUP_EXTRA_BLKS (D_N * EXTRA_N / 256)

__global__ void __launch_bounds__(256) setup_kernel(const float* __restrict__ z,
                                                    const int* __restrict__ seed_ptr) {
    int b = blockIdx.x;
    if (b < SETUP_POOL_BLKS) {
        int i = b * 256 + threadIdx.x;
        uint32_t k1 = (uint32_t)seed_ptr[0];
        uint32_t o0, o1;
        threefry2x32(0u, k1, 0u, (uint32_t)i, o0, o1);
        g_Apool[i] = bits_to_normal(o0 ^ o1);
    } else if (b < SETUP_POOL_BLKS + SETUP_CM_BLKS) {
        __shared__ float2 sm[4][64];
        int xb = b - SETUP_POOL_BLKS;
        int x = threadIdx.x & 63, y = threadIdx.x >> 6;
        int c = xb * 64 + x;
        float s = 0.f, comp = 0.f;
        for (int r = y; r < B_N; r += 4) {
            float v = z[(size_t)r * D_N + c];
            float yv = v - comp;
            float t = s + yv;
            comp = (t - s) - yv;
            s = t;
        }
        sm[y][x] = make_float2(s, comp);
        __syncthreads();
        if (y == 0) {
            double tot = 0.0;
            for (int w = 0; w < 4; w++) {
                float2 p = sm[w][x];
                tot += (double)p.x - (double)p.y;
            }
            g_means[c] = (float)(tot * (1.0 / 2048.0));
        }
    } else {
        int i = (b - SETUP_POOL_BLKS - SETUP_CM_BLKS) * 256 + threadIdx.x;
        uint32_t k1 = (uint32_t)(seed_ptr[0] + 9991);
        uint32_t o0, o1;
        threefry2x32(0u, k1, 0u, (uint32_t)i, o0, o1);
        g_R[i] = bits_to_normal(o0 ^ o1);
    }
}

/* ------------------------------------------------------------------ */
/* Column normalize                                                   */
/* ------------------------------------------------------------------ */
__device__ __forceinline__ void norm_cols_body(float* A, int nc, int col) {
    __shared__ float2 sm[16][64];
    __shared__ float sden[64];
    int x = threadIdx.x, y = threadIdx.y;
    float s = 0.f, comp = 0.f;
    for (int r = 0; r < 64; r++) {
        int d = y * 64 + r;
        float v = A[(size_t)d * nc + col];
        float v2 = v * v;
        float yv = v2 - comp;
        float t = s + yv;
        comp = (t - s) - yv;
        s = t;
    }
    sm[y][x] = make_float2(s, comp);
    __syncthreads();
    if (y == 0) {
        double tot = 0.0;
        for (int w = 0; w < 16; w++) {
            float2 p = sm[w][x];
            tot += (double)p.x - (double)p.y;
        }
        sden[x] = (float)sqrt(tot) + 1e-12f;
    }
    __syncthreads();
    float den = sden[x];
    for (int r = 0; r < 64; r++) {
        int d = y * 64 + r;
        A[(size_t)d * nc + col] /= den;
    }
}

__global__ void norm_comb_kernel() {
    if (blockIdx.x < 32)
        norm_cols_body(g_Apool, POOL_N, blockIdx.x * 64 + threadIdx.x);
    else
        norm_cols_body(g_R, EXTRA_N, threadIdx.x);
}

__global__ void norm_cols_kernel(int which) {
    float* A = which ? g_R : g_Apool;
    int nc   = which ? EXTRA_N : POOL_N;
    norm_cols_body(A, nc, blockIdx.x * 64 + threadIdx.x);
}

/* ------------------------------------------------------------------ */
/* GEMM0: 128x128 tile, 256 thr, 2 CTAs/SM, f32x2, double-buffered    */
/* ------------------------------------------------------------------ */
__global__ void __launch_bounds__(256, 2) gemm0_kernel(const float* __restrict__ z) {
    __shared__ __align__(16) float As[2][8][BM + 4];
    __shared__ __align__(16) float Bs[2][8][BN + 4];

    int tid = threadIdx.x;
    int tx = tid & 15;
    int ty = tid >> 4;
    int m0 = blockIdx.y * BM, n0 = blockIdx.x * BN;

    int a_row = tid >> 1;
    int a_k4  = (tid & 1) * 4;
    int b_k   = tid >> 5;
    int b_n4  = (tid & 31) * 4;

    const float* Ap = z + (size_t)(m0 + a_row) * D_N + a_k4;
    const float* Bp = g_Apool + (size_t)b_k * POOL_N + n0 + b_n4;

    unsigned long long acc[8][4];
#pragma unroll
    for (int i = 0; i < 8; i++)
#pragma unroll
        for (int jp = 0; jp < 4; jp++) acc[i][jp] = 0ull;

    float4 av = *(const float4*)Ap;
    float4 mv = *(const float4*)(g_means + a_k4);
    float4 bv = *(const float4*)Bp;

    for (int c = 0; c < D_N / 8; c++) {
        int buf = c & 1;
        As[buf][a_k4 + 0][a_row] = av.x - mv.x;
        As[buf][a_k4 + 1][a_row] = av.y - mv.y;
        As[buf][a_k4 + 2][a_row] = av.z - mv.z;
        As[buf][a_k4 + 3][a_row] = av.w - mv.w;
        *(float4*)&Bs[buf][b_k][b_n4] = bv;
        __syncthreads();
        if (c + 1 < D_N / 8) {
            int k0 = (c + 1) * 8;
            av = *(const float4*)(Ap + k0);
            mv = *(const float4*)(g_means + k0 + a_k4);
            bv = *(const float4*)(Bp + (size_t)k0 * POOL_N);
        }
#pragma unroll
        for (int kk = 0; kk < 8; kk++) {
            float4 a0 = *(const float4*)&As[buf][kk][ty * 8];
            float4 a1 = *(const float4*)&As[buf][kk][ty * 8 + 4];
            ulonglong2 b0 = *(const ulonglong2*)&Bs[buf][kk][tx * 8];
            ulonglong2 b1 = *(const ulonglong2*)&Bs[buf][kk][tx * 8 + 4];
            unsigned long long a2[8];
            a2[0] = bcast2(a0.x); a2[1] = bcast2(a0.y);
            a2[2] = bcast2(a0.z); a2[3] = bcast2(a0.w);
            a2[4] = bcast2(a1.x); a2[5] = bcast2(a1.y);
            a2[6] = bcast2(a1.z); a2[7] = bcast2(a1.w);
#pragma unroll
            for (int i = 0; i < 8; i++) {
                fma2(acc[i][0], a2[i], b0.x);
                fma2(acc[i][1], a2[i], b0.y);
                fma2(acc[i][2], a2[i], b1.x);
                fma2(acc[i][3], a2[i], b1.y);
            }
        }
    }

#pragma unroll
    for (int jp = 0; jp < 4; jp++) {
        float lo[8], hi[8];
#pragma unroll
        for (int i = 0; i < 8; i++) {
            float2 p = unpk2(acc[i][jp]);
            lo[i] = p.x; hi[i] = p.y;
        }
        int ne = n0 + tx * 8 + 2 * jp;
        float* be = &g_ut[(size_t)ne * B_N + m0 + ty * 8];
        float* bo = &g_ut[(size_t)(ne + 1) * B_N + m0 + ty * 8];
        *(float4*)be       = make_float4(lo[0], lo[1], lo[2], lo[3]);
        *(float4*)(be + 4) = make_float4(lo[4], lo[5], lo[6], lo[7]);
        *(float4*)bo       = make_float4(hi[0], hi[1], hi[2], hi[3]);
        *(float4*)(bo + 4) = make_float4(hi[4], hi[5], hi[6], hi[7]);
    }
}

/* ------------------------------------------------------------------ */
/* GEMM1 (final): 64x64 tiles, f32x2                                  */
/* ------------------------------------------------------------------ */
__global__ void __launch_bounds__(256) gemm1_kernel(const float* __restrict__ z) {
    __shared__ __align__(16) float As[16][68];
    __shared__ __align__(16) float Bs[16][68];

    int tid = threadIdx.x;
    int tx = tid & 15, ty = tid >> 4;
    int m0 = blockIdx.y * 64, n0 = blockIdx.x * 64;

    int a_row = tid & 63;
    int a_k4  = (tid >> 6) * 4;
    int b_k   = tid >> 4;
    int b_n4  = (tid & 15) * 4;

    const float* Ap = z + (size_t)(m0 + a_row) * D_N + a_k4;
    const float* Bp = g_Afin + (size_t)b_k * AFIN_N + n0 + b_n4;

    unsigned long long acc[4][2];
#pragma unroll
    for (int i = 0; i < 4; i++) { acc[i][0] = 0ull; acc[i][1] = 0ull; }

    for (int k0 = 0; k0 < D_N; k0 += 16) {
        float4 av = *(const float4*)(Ap + k0);
        float4 mv = *(const float4*)(g_means + k0 + a_k4);
        float4 bv = *(const float4*)(Bp + (size_t)k0 * AFIN_N);
        av.x -= mv.x; av.y -= mv.y; av.z -= mv.z; av.w -= mv.w;
        __syncthreads();
        As[a_k4 + 0][a_row] = av.x;
        As[a_k4 + 1][a_row] = av.y;
        As[a_k4 + 2][a_row] = av.z;
        As[a_k4 + 3][a_row] = av.w;
        *(float4*)&Bs[b_k][b_n4] = bv;
        __syncthreads();
#pragma unroll
        for (int kk = 0; kk < 16; kk++) {
            float4 a = *(const float4*)&As[kk][ty * 4];
            ulonglong2 b = *(const ulonglong2*)&Bs[kk][tx * 4];
            unsigned long long a2[4];
            a2[0] = bcast2(a.x); a2[1] = bcast2(a.y);
            a2[2] = bcast2(a.z); a2[3] = bcast2(a.w);
#pragma unroll
            for (int i = 0; i < 4; i++) {
                fma2(acc[i][0], a2[i], b.x);
                fma2(acc[i][1], a2[i], b.y);
            }
        }
    }
#pragma unroll
    for (int jp = 0; jp < 2; jp++) {
        int ne = n0 + tx * 4 + 2 * jp;
#pragma unroll
        for (int i = 0; i < 4; i++) {
            float2 p = unpk2(acc[i][jp]);
            int m = m0 + ty * 4 + i;
            g_u2t[(size_t)ne * B_N + m]       = p.x;
            g_u2t[(size_t)(ne + 1) * B_N + m] = p.y;
        }
    }
}

/* ------------------------------------------------------------------ */
/* ECF slice loss                                                     */
/* ------------------------------------------------------------------ */
__device__ __forceinline__ void ecf_sample(float x, float ar[8], float ai[8]) {
    float s1, c1;
    __sincosf(x, &s1, &c1);
    float twoc = c1 + c1;
    float cm = 1.f, sm = 0.f;
    float c = c1, s = s1;
#pragma unroll
    for (int j = 0; j < 8; j++) {
        ar[j] += c; ai[j] += s;
        float cn = fmaf(twoc, c, -cm);
        float sn = fmaf(twoc, s, -sm);
        cm = c; sm = s; c = cn; s = sn;
    }
}

__global__ void __launch_bounds__(256) ecf_kernel(int which) {
    const float*  __restrict__ ut = which ? g_u2t : g_ut;
    double*       __restrict__ L  = which ? g_floss : g_losses;
    int a = blockIdx.x;
    int t = threadIdx.x;
    int lane = t & 31, warp = t >> 5;
    const float4* row4 = (const float4*)(ut + (size_t)a * B_N);

    float ar[8], ai[8];
#pragma unroll
    for (int j = 0; j < 8; j++) { ar[j] = 0.f; ai[j] = 0.f; }

#pragma unroll
    for (int it = 0; it < 2; it++) {
        float4 xv = row4[t + 256 * it];
        ecf_sample(0.625f * xv.x, ar, ai);
        ecf_sample(0.625f * xv.y, ar, ai);
        ecf_sample(0.625f * xv.z, ar, ai);
        ecf_sample(0.625f * xv.w, ar, ai);
    }

    __shared__ float sred[8][16];
    __shared__ double sredd[16];
#pragma unroll
    for (int q = 0; q < 16; q++) {
        float v = (q < 8) ? ar[q] : ai[q - 8];
#pragma unroll
        for (int o = 16; o; o >>= 1) v += __shfl_xor_sync(0xffffffffu, v, o);
        if (lane == 0) sred[warp][q] = v;
    }
    __syncthreads();
    if (t < 16) {
        double tot = 0.0;
        for (int w = 0; w < 8; w++) tot += (double)sred[w][t];
        sredd[t] = tot;
    }
    __syncthreads();
    if (t == 0) {
        const double invB = 1.0 / 2048.0;
        double loss = 0.0;
#pragma unroll
        for (int j = 1; j <= 8; j++) {
            double tj = 0.625 * (double)j;
            double ph = exp(-0.5 * tj * tj);
            double re = sredd[j - 1] * invB - ph;
            double im = sredd[8 + j - 1] * invB;
            double integ = (re * re + im * im) * ph;
            loss += ((j == 8) ? 0.625 : 1.25) * integ;
        }
        L[a] = loss;
    }
}

/* ------------------------------------------------------------------ */
/* Bitonic sort                                                       */
/* ------------------------------------------------------------------ */
__global__ void __launch_bounds__(1024) sort_kernel() {
    __shared__ long long sv[2048];
    __shared__ int       si[2048];
    int t = threadIdx.x;
    for (int i = t; i < 2048; i += 1024) {
        sv[i] = __double_as_longlong(g_losses[i]);
        si[i] = i;
    }
    __syncthreads();
    for (int k = 2; k <= 2048; k <<= 1) {
        for (int jj = k >> 1; jj > 0; jj >>= 1) {
            for (int i = t; i < 2048; i += 1024) {
                int ixj = i ^ jj;
                if (ixj > i) {
                    long long va = sv[i], vb = sv[ixj];
                    int       ia = si[i], ib = si[ixj];
                    bool aFirst = (va > vb) || (va == vb && ia < ib);
                    bool dirAsc = ((i & k) == 0);
                    if (aFirst != dirAsc) {
                        sv[i] = vb; sv[ixj] = va;
                        si[i] = ib; si[ixj] = ia;
                    }
                }
            }
            __syncthreads();
        }
    }
    for (int i = t; i < HARD_N; i += 1024) g_ranked[i] = si[i];
}

/* ------------------------------------------------------------------ */
/* GS via Cholesky                                                    */
/* ------------------------------------------------------------------ */
__global__ void gather_kernel() {
    int idx = blockIdx.x * 256 + threadIdx.x;
    int i = idx >> 10, d = idx & 1023;
    g_H[idx] = g_Apool[(size_t)d * POOL_N + g_ranked[i]];
}

__global__ void __launch_bounds__(256) syrk_kernel() {
    int i = blockIdx.x;
    __shared__ float hi[D_N];
    int tid = threadIdx.x;
    *(float4*)&hi[tid * 4] = *(const float4*)&g_H[(size_t)i * D_N + tid * 4];
    __syncthreads();
    int lane = tid & 31, warp = tid >> 5;
    const float4* hi4 = (const float4*)hi;
    for (int j = warp; j < HARD_N; j += 8) {
        const float4* hj = (const float4*)&g_H[(size_t)j * D_N];
        float acc = 0.f;
        for (int d4 = lane; d4 < 256; d4 += 32) {
            float4 a = hi4[d4];
            float4 b = hj[d4];
            acc = fmaf(a.x, b.x, fmaf(a.y, b.y, fmaf(a.z, b.z, fmaf(a.w, b.w, acc))));
        }
#pragma unroll
        for (int o = 16; o; o >>= 1) acc += __shfl_down_sync(0xffffffffu, acc, o);
        if (lane == 0) g_G[i * HARD_N + j] = acc;
    }
}

/* Cholesky only: writes R (upper-tri incl diag) back over g_G        */
__global__ void __launch_bounds__(128) cholinv_kernel() {
    extern __shared__ float sbuf[];
    float* sR = sbuf;
    int m = threadIdx.x;
    __shared__ float sdiag;

    for (int k = 0; k < HARD_N; k++)
        sR[k * HARD_N + m] = g_G[k * HARD_N + m];
    __syncthreads();

    for (int j = 0; j < HARD_N; j++) {
        float s[8];
#pragma unroll
        for (int u = 0; u < 8; u++) s[u] = 0.f;
        int k = 0;
        for (; k + 8 <= j; k += 8) {
#pragma unroll
            for (int u = 0; u < 8; u++)
                s[u] = fmaf(sR[(k + u) * HARD_N + j], sR[(k + u) * HARD_N + m], s[u]);
        }
        for (int u = 0; k < j; k++, u++)
            s[u] = fmaf(sR[k * HARD_N + j], sR[k * HARD_N + m], s[u]);
        float smm = ((s[0] + s[1]) + (s[2] + s[3])) + ((s[4] + s[5]) + (s[6] + s[7]));
        if (m == j) {
            float dd = sR[j * HARD_N + j] - smm;
            float r  = sqrtf(fmaxf(dd, 0.f));
            sdiag = fmaxf(r, 1e-12f);
        }
        __syncthreads();
        float rjj = sdiag;
        if (m > j)       sR[j * HARD_N + m] = (sR[j * HARD_N + m] - smm) / rjj;
        else if (m == j) sR[j * HARD_N + j] = rjj;
        __syncthreads();
    }

    for (int k = 0; k < HARD_N; k++)
        g_G[k * HARD_N + m] = sR[k * HARD_N + m];
}

/* T = R^{-1}, one block per column jc; R in g_G                      */
__global__ void __launch_bounds__(128) trinv_kernel() {
    __shared__ float t[HARD_N];
    __shared__ float red[4];
    int jc = blockIdx.x;
    int tid = threadIdx.x;
    int lane = tid & 31, warp = tid >> 5;

    if (tid == 0) t[jc] = 1.f / g_G[jc * HARD_N + jc];
    __syncthreads();

    for (int i = jc - 1; i >= 0; i--) {
        int k = i + 1 + tid;
        float part = (k <= jc) ? g_G[i * HARD_N + k] * t[k] : 0.f;
#pragma unroll
        for (int o = 16; o; o >>= 1) part += __shfl_xor_sync(0xffffffffu, part, o);
        if (lane == 0) red[warp] = part;
        __syncthreads();
        if (tid == 0) {
            float tot = (red[0] + red[1]) + (red[2] + red[3]);
            t[i] = -tot / g_G[i * HARD_N + i];
        }
        __syncthreads();
    }

    if (tid < HARD_N)
        g_T[tid * HARD_N + jc] = (tid <= jc) ? t[tid] : 0.f;
}

__global__ void __launch_bounds__(256) qht_kernel() {
    int j = threadIdx.x & 127;
    int d = blockIdx.x * 2 + (threadIdx.x >> 7);
    float a0 = 0.f, a1 = 0.f;
    for (int k = 0; k < HARD_N; k += 2) {
        float h0 = g_H[(size_t)k * D_N + d];
        float h1 = g_H[(size_t)(k + 1) * D_N + d];
        a0 = fmaf(h0, g_T[k * HARD_N + j], a0);
        a1 = fmaf(h1, g_T[(k + 1) * HARD_N + j], a1);
    }
    g_Q[(size_t)j * D_N + d] = a0 + a1;
}

/* ------------------------------------------------------------------ */
/* Extra directions                                                   */
/* ------------------------------------------------------------------ */
__global__ void qtr_kernel() {
    __shared__ float sm[4][64];
    int i = blockIdx.x;
    int j = threadIdx.x, dq = threadIdx.y;
    const float* qp = g_Q + (size_t)i * D_N + dq * 256;
    const float* r = g_R + (size_t)(dq * 256) * EXTRA_N + j;
    float s = 0.f;
#pragma unroll 4
    for (int d = 0; d < 256; d++)
        s = fmaf(qp[d], r[(size_t)d * EXTRA_N], s);
    sm[dq][j] = s;
    __syncthreads();
    if (dq == 0) {
        double t = (double)sm[0][j] + (double)sm[1][j]
                 + (double)sm[2][j] + (double)sm[3][j];
        g_C[i * EXTRA_N + j] = (float)t;
    }
}

__global__ void subproj_kernel() {
    int idx = blockIdx.x * blockDim.x + threadIdx.x;
    int d = idx >> 6, j = idx & 63;
    float s = 0.f;
    for (int i = 0; i < HARD_N; i++)
        s = fmaf(g_Q[(size_t)i * D_N + d], g_C[i * EXTRA_N + j], s);
    g_R[idx] -= s;
}

__global__ void assemble_kernel() {
    int idx = blockIdx.x * blockDim.x + threadIdx.x;
    int d = idx >> 8, c = idx & 255;
    float v = 0.f;
    if (c < HARD_N)      v = g_Q[(size_t)c * D_N + d];
    else if (c < NFIN)   v = g_R[(size_t)d * EXTRA_N + (c - HARD_N)];
    g_Afin[idx] = v;
}

__global__ void final_kernel(float* __restrict__ out) {
    __shared__ double sh[256];
    int t = threadIdx.x;
    sh[t] = (t < NFIN) ? g_floss[t] : 0.0;
    __syncthreads();
    if (t == 0) {
        double s = 0.0;
        for (int i = 0; i < NFIN; i++) s += sh[i];
        out[0] = (float)((s / 192.0) * 2048.0);
    }
}

/* ------------------------------------------------------------------ */
extern "C" void kernel_launch(void* const* d_in, const int* in_sizes, int n_in,
                              void* d_out, int out_size) {
    const float* z; const int* seed;
    if (in_sizes[0] == 1) { seed = (const int*)d_in[0]; z = (const float*)d_in[1]; }
    else                  { z = (const float*)d_in[0]; seed = (const int*)d_in[1]; }
    float* out = (float*)d_out;

    static int smem_set = 0;
    if (!smem_set) {
        cudaFuncSetAttribute(cholinv_kernel,
                             cudaFuncAttributeMaxDynamicSharedMemorySize,
                             HARD_N * HARD_N * (int)sizeof(float));
        smem_set = 1;
    }

    setup_kernel<<<SETUP_POOL_BLKS + SETUP_CM_BLKS + SETUP_EXTRA_BLKS, 256>>>(z, seed);
    norm_comb_kernel<<<33, dim3(64, 16)>>>();

    gemm0_kernel<<<dim3(POOL_N / BN, B_N / BM), 256>>>(z);
    ecf_kernel<<<POOL_N, 256>>>(0);

    sort_kernel<<<1, 1024>>>();

    gather_kernel<<<(HARD_N * D_N) / 256, 256>>>();
    syrk_kernel<<<HARD_N, 256>>>();
    cholinv_kernel<<<1, 128, HARD_N * HARD_N * sizeof(float)>>>();
    trinv_kernel<<<HARD_N, 128>>>();
    qht_kernel<<<D_N / 2, 256>>>();

    qtr_kernel<<<HARD_N, dim3(64, 4)>>>();
    subproj_kernel<<<(D_N * EXTRA_N) / 256, 256>>>();
    norm_cols_kernel<<<1, dim3(64, 16)>>>(1);

    assemble_kernel<<<(D_N * AFIN_N) / 256, 256>>>();
    gemm1_kernel<<<dim3(NFIN / 64, B_N / 64), 256>>>(z);
    ecf_kernel<<<NFIN, 256>>>(1);

    final_kernel<<<1, 256>>>(out);
}